// round 1
// baseline (speedup 1.0000x reference)
#include <cuda_runtime.h>
#include <math.h>

#define T_SEQ 2048
#define CDIM  1024
#define NB    2
#define NH    16
#define HD    64
#define MTOK  (NB * T_SEQ)   // 4096 token rows

// Scratch (static device globals: allocation-free per harness rules)
__device__ float g_q  [(size_t)MTOK * CDIM];
__device__ float g_k  [(size_t)MTOK * CDIM];
__device__ float g_v  [(size_t)MTOK * CDIM];
__device__ float g_att[(size_t)MTOK * CDIM];

// ---------------------------------------------------------------------------
// NT GEMM: Y[M,N] = X[M,K] @ W[N,K]^T  (+ cb[n]*cv[m,n])  (+ bias[n])
// BM=BN=128, BK=16, 256 threads, 8x8 register tile per thread.
// M,N,K all multiples of tile sizes for this problem (4096/1024/1024).
// ---------------------------------------------------------------------------
__global__ __launch_bounds__(256) void gemm_nt(
    const float* __restrict__ X, const float* __restrict__ W,
    float* __restrict__ Y, int M, int N, int K,
    const float* __restrict__ cv, const float* __restrict__ cb,
    const float* __restrict__ bias)
{
    __shared__ float Xs[16 * 132];
    __shared__ float Ws[16 * 132];

    const int tid = threadIdx.x;
    const int tx = tid & 15;
    const int ty = tid >> 4;
    const int m0 = blockIdx.y * 128;
    const int n0 = blockIdx.x * 128;

    float acc[8][8];
#pragma unroll
    for (int i = 0; i < 8; ++i)
#pragma unroll
        for (int j = 0; j < 8; ++j) acc[i][j] = 0.0f;

    for (int k0 = 0; k0 < K; k0 += 16) {
        // Stage X and W tiles (transposed into [k][m] / [k][n])
#pragma unroll
        for (int it = 0; it < 2; ++it) {
            int idx = tid + it * 256;          // 0..511
            int r   = idx >> 2;                // 0..127
            int k4  = (idx & 3) * 4;           // 0,4,8,12
            float4 vx = *(const float4*)(X + (size_t)(m0 + r) * K + k0 + k4);
            Xs[(k4 + 0) * 132 + r] = vx.x;
            Xs[(k4 + 1) * 132 + r] = vx.y;
            Xs[(k4 + 2) * 132 + r] = vx.z;
            Xs[(k4 + 3) * 132 + r] = vx.w;
            float4 vw = *(const float4*)(W + (size_t)(n0 + r) * K + k0 + k4);
            Ws[(k4 + 0) * 132 + r] = vw.x;
            Ws[(k4 + 1) * 132 + r] = vw.y;
            Ws[(k4 + 2) * 132 + r] = vw.z;
            Ws[(k4 + 3) * 132 + r] = vw.w;
        }
        __syncthreads();

#pragma unroll
        for (int kk = 0; kk < 16; ++kk) {
            float a[8], b[8];
            *(float4*)&a[0] = *(float4*)&Xs[kk * 132 + ty * 8];
            *(float4*)&a[4] = *(float4*)&Xs[kk * 132 + ty * 8 + 4];
            *(float4*)&b[0] = *(float4*)&Ws[kk * 132 + tx * 8];
            *(float4*)&b[4] = *(float4*)&Ws[kk * 132 + tx * 8 + 4];
#pragma unroll
            for (int i = 0; i < 8; ++i)
#pragma unroll
                for (int j = 0; j < 8; ++j)
                    acc[i][j] = fmaf(a[i], b[j], acc[i][j]);
        }
        __syncthreads();
    }

    // Epilogue
#pragma unroll
    for (int i = 0; i < 8; ++i) {
        const int row = m0 + ty * 8 + i;
#pragma unroll
        for (int j = 0; j < 8; ++j) {
            const int col = n0 + tx * 8 + j;
            float v = acc[i][j];
            if (cb)   v += cb[col] * cv[(size_t)row * N + col];
            if (bias) v += bias[col];
            Y[(size_t)row * N + col] = v;
        }
    }
}

// ---------------------------------------------------------------------------
// Causal flash attention. One block = one (b,h) and one 64-row Q tile.
// 256 threads, 4x4 register tiles over the 64x64 S / O tiles.
// Online softmax (running max/sum), K/V/P staged in dynamic smem.
// ---------------------------------------------------------------------------
__global__ __launch_bounds__(256) void attn_kernel(
    const float* __restrict__ gq, const float* __restrict__ gk,
    const float* __restrict__ gv, float* __restrict__ go)
{
    extern __shared__ float sm[];
    float* Qs = sm;                 // [64][68]
    float* Ks = sm + 64 * 68;       // [64][68]
    float* Vs = sm + 2 * 64 * 68;   // [64][68]
    float* Ps = sm + 3 * 64 * 68;   // [64][68]

    const int tid = threadIdx.x;
    const int tx = tid & 15;
    const int ty = tid >> 4;
    const int qt = blockIdx.x;               // q tile index (0..31)
    const int bh = blockIdx.y;               // 0..31
    const int b  = bh >> 4;
    const int h  = bh & 15;

    const size_t base = ((size_t)b * T_SEQ) * CDIM + (size_t)h * HD;

    // Load Q tile [64 x 64]
#pragma unroll
    for (int it = 0; it < 4; ++it) {
        int idx = tid + it * 256;            // 0..1023
        int r   = idx >> 4;                  // 0..63
        int c4  = (idx & 15) * 4;            // 0..60
        *(float4*)&Qs[r * 68 + c4] =
            *(const float4*)(gq + base + (size_t)(qt * 64 + r) * CDIM + c4);
    }

    float m_i[4], l_i[4], o[4][4];
#pragma unroll
    for (int i = 0; i < 4; ++i) {
        m_i[i] = -INFINITY;
        l_i[i] = 0.0f;
#pragma unroll
        for (int j = 0; j < 4; ++j) o[i][j] = 0.0f;
    }

    for (int kt = 0; kt <= qt; ++kt) {
        // Load K and V tiles
#pragma unroll
        for (int it = 0; it < 4; ++it) {
            int idx = tid + it * 256;
            int r   = idx >> 4;
            int c4  = (idx & 15) * 4;
            size_t g = base + (size_t)(kt * 64 + r) * CDIM + c4;
            *(float4*)&Ks[r * 68 + c4] = *(const float4*)(gk + g);
            *(float4*)&Vs[r * 68 + c4] = *(const float4*)(gv + g);
        }
        __syncthreads();

        // S = Q K^T * 1/8
        float s[4][4];
#pragma unroll
        for (int i = 0; i < 4; ++i)
#pragma unroll
            for (int j = 0; j < 4; ++j) s[i][j] = 0.0f;

#pragma unroll 8
        for (int d = 0; d < 64; ++d) {
            float a0 = Qs[(ty * 4 + 0) * 68 + d];
            float a1 = Qs[(ty * 4 + 1) * 68 + d];
            float a2 = Qs[(ty * 4 + 2) * 68 + d];
            float a3 = Qs[(ty * 4 + 3) * 68 + d];
            float b0 = Ks[(tx * 4 + 0) * 68 + d];
            float b1 = Ks[(tx * 4 + 1) * 68 + d];
            float b2 = Ks[(tx * 4 + 2) * 68 + d];
            float b3 = Ks[(tx * 4 + 3) * 68 + d];
            s[0][0] = fmaf(a0, b0, s[0][0]); s[0][1] = fmaf(a0, b1, s[0][1]);
            s[0][2] = fmaf(a0, b2, s[0][2]); s[0][3] = fmaf(a0, b3, s[0][3]);
            s[1][0] = fmaf(a1, b0, s[1][0]); s[1][1] = fmaf(a1, b1, s[1][1]);
            s[1][2] = fmaf(a1, b2, s[1][2]); s[1][3] = fmaf(a1, b3, s[1][3]);
            s[2][0] = fmaf(a2, b0, s[2][0]); s[2][1] = fmaf(a2, b1, s[2][1]);
            s[2][2] = fmaf(a2, b2, s[2][2]); s[2][3] = fmaf(a2, b3, s[2][3]);
            s[3][0] = fmaf(a3, b0, s[3][0]); s[3][1] = fmaf(a3, b1, s[3][1]);
            s[3][2] = fmaf(a3, b2, s[3][2]); s[3][3] = fmaf(a3, b3, s[3][3]);
        }

        const float sc = 0.125f;           // 1/sqrt(64)
        const int qrow0 = qt * 64 + ty * 4;
        const int kcol0 = kt * 64 + tx * 4;
#pragma unroll
        for (int i = 0; i < 4; ++i)
#pragma unroll
            for (int j = 0; j < 4; ++j) {
                float v = s[i][j] * sc;
                if (kcol0 + j > qrow0 + i) v = -INFINITY;  // causal
                s[i][j] = v;
            }

        // Online softmax per row (reduce across the 16-lane tx group)
#pragma unroll
        for (int i = 0; i < 4; ++i) {
            float rm = fmaxf(fmaxf(s[i][0], s[i][1]), fmaxf(s[i][2], s[i][3]));
#pragma unroll
            for (int off = 8; off; off >>= 1)
                rm = fmaxf(rm, __shfl_xor_sync(0xffffffffu, rm, off));
            float m_new = fmaxf(m_i[i], rm);
            float corr  = expf(m_i[i] - m_new);
            float rs = 0.0f;
#pragma unroll
            for (int j = 0; j < 4; ++j) {
                float p = expf(s[i][j] - m_new);
                s[i][j] = p;
                rs += p;
            }
#pragma unroll
            for (int off = 8; off; off >>= 1)
                rs += __shfl_xor_sync(0xffffffffu, rs, off);
            l_i[i] = l_i[i] * corr + rs;
            m_i[i] = m_new;
#pragma unroll
            for (int j = 0; j < 4; ++j) o[i][j] *= corr;
#pragma unroll
            for (int j = 0; j < 4; ++j)
                Ps[(ty * 4 + i) * 68 + tx * 4 + j] = s[i][j];
        }
        __syncthreads();   // Ps visible; also all S reads of Ks done

        // O += P @ V
#pragma unroll 8
        for (int c = 0; c < 64; ++c) {
            float p0 = Ps[(ty * 4 + 0) * 68 + c];
            float p1 = Ps[(ty * 4 + 1) * 68 + c];
            float p2 = Ps[(ty * 4 + 2) * 68 + c];
            float p3 = Ps[(ty * 4 + 3) * 68 + c];
            float4 vv = *(float4*)&Vs[c * 68 + tx * 4];
            o[0][0] = fmaf(p0, vv.x, o[0][0]); o[0][1] = fmaf(p0, vv.y, o[0][1]);
            o[0][2] = fmaf(p0, vv.z, o[0][2]); o[0][3] = fmaf(p0, vv.w, o[0][3]);
            o[1][0] = fmaf(p1, vv.x, o[1][0]); o[1][1] = fmaf(p1, vv.y, o[1][1]);
            o[1][2] = fmaf(p1, vv.z, o[1][2]); o[1][3] = fmaf(p1, vv.w, o[1][3]);
            o[2][0] = fmaf(p2, vv.x, o[2][0]); o[2][1] = fmaf(p2, vv.y, o[2][1]);
            o[2][2] = fmaf(p2, vv.z, o[2][2]); o[2][3] = fmaf(p2, vv.w, o[2][3]);
            o[3][0] = fmaf(p3, vv.x, o[3][0]); o[3][1] = fmaf(p3, vv.y, o[3][1]);
            o[3][2] = fmaf(p3, vv.z, o[3][2]); o[3][3] = fmaf(p3, vv.w, o[3][3]);
        }
        __syncthreads();   // protect Ks/Vs/Ps before next iteration's loads
    }

    // Write O tile (normalized) into [B,T,C] layout
#pragma unroll
    for (int i = 0; i < 4; ++i) {
        const float inv = 1.0f / l_i[i];
        const int row = qt * 64 + ty * 4 + i;
#pragma unroll
        for (int j = 0; j < 4; ++j)
            go[base + (size_t)row * CDIM + tx * 4 + j] = o[i][j] * inv;
    }
}

// ---------------------------------------------------------------------------
// Launch
// Inputs (metadata order): 0:x 1:mask 2:context_vector 3:w_q 4:w_k 5:w_v
//                          6:w_o 7:b_o 8:context_bias   out: f32 [2,2048,1024]
// ---------------------------------------------------------------------------
extern "C" void kernel_launch(void* const* d_in, const int* in_sizes, int n_in,
                              void* d_out, int out_size)
{
    (void)in_sizes; (void)n_in; (void)out_size;
    const float* x  = (const float*)d_in[0];
    // d_in[1] is the causal mask (tril) — structure is hardcoded in attn_kernel
    const float* cv = (const float*)d_in[2];
    const float* wq = (const float*)d_in[3];
    const float* wk = (const float*)d_in[4];
    const float* wv = (const float*)d_in[5];
    const float* wo = (const float*)d_in[6];
    const float* bo = (const float*)d_in[7];
    const float* cb = (const float*)d_in[8];
    float* out = (float*)d_out;

    float *q, *k, *v, *att;
    cudaGetSymbolAddress((void**)&q,   g_q);
    cudaGetSymbolAddress((void**)&k,   g_k);
    cudaGetSymbolAddress((void**)&v,   g_v);
    cudaGetSymbolAddress((void**)&att, g_att);

    const dim3 ggrid(CDIM / 128, MTOK / 128);   // (8, 32)
    gemm_nt<<<ggrid, 256>>>(x, wq, q, MTOK, CDIM, CDIM, cv, cb, nullptr);
    gemm_nt<<<ggrid, 256>>>(x, wk, k, MTOK, CDIM, CDIM, nullptr, nullptr, nullptr);
    gemm_nt<<<ggrid, 256>>>(x, wv, v, MTOK, CDIM, CDIM, nullptr, nullptr, nullptr);

    const int smem = 4 * 64 * 68 * sizeof(float);   // 69632 B
    cudaFuncSetAttribute(attn_kernel, cudaFuncAttributeMaxDynamicSharedMemorySize, smem);
    attn_kernel<<<dim3(T_SEQ / 64, NB * NH), 256, smem>>>(q, k, v, att);

    gemm_nt<<<ggrid, 256>>>(att, wo, out, MTOK, CDIM, CDIM, nullptr, nullptr, bo);
}

// round 3
// speedup vs baseline: 1.7952x; 1.7952x over previous
#include <cuda_runtime.h>
#include <cuda_bf16.h>
#include <math.h>
#include <stdint.h>

#define T_SEQ 2048
#define CDIM  1024
#define NB    2
#define NH    16
#define HD    64
#define MTOK  (NB * T_SEQ)   // 4096 token rows

// ---------------------------------------------------------------------------
// Scratch (static device globals: allocation-free per harness rules)
// ---------------------------------------------------------------------------
__device__ float g_q  [(size_t)MTOK * CDIM];
__device__ float g_k  [(size_t)MTOK * CDIM];
__device__ float g_v  [(size_t)MTOK * CDIM];
__device__ float g_att[(size_t)MTOK * CDIM];
__device__ __nv_bfloat16 g_ahi[(size_t)MTOK * CDIM];
__device__ __nv_bfloat16 g_alo[(size_t)MTOK * CDIM];
__device__ __nv_bfloat16 g_whi[(size_t)CDIM * CDIM];
__device__ __nv_bfloat16 g_wlo[(size_t)CDIM * CDIM];

// ---------------------------------------------------------------------------
// Helpers
// ---------------------------------------------------------------------------
__device__ __forceinline__ uint32_t smem_u32(const void* p) {
    uint32_t a;
    asm("{ .reg .u64 t; cvta.to.shared.u64 t, %1; cvt.u32.u64 %0, t; }"
        : "=r"(a) : "l"(p));
    return a;
}
__device__ __forceinline__ float ex2f(float x) {
    float y; asm("ex2.approx.ftz.f32 %0, %1;" : "=f"(y) : "f"(x)); return y;
}
__device__ __forceinline__ void ldsm4(uint32_t& r0, uint32_t& r1,
                                      uint32_t& r2, uint32_t& r3, uint32_t addr) {
    asm volatile("ldmatrix.sync.aligned.m8n8.x4.shared.b16 {%0,%1,%2,%3}, [%4];"
                 : "=r"(r0), "=r"(r1), "=r"(r2), "=r"(r3) : "r"(addr));
}
__device__ __forceinline__ void mma16816(float* c, const uint32_t* a, const uint32_t* b) {
    asm volatile(
        "mma.sync.aligned.m16n8k16.row.col.f32.bf16.bf16.f32 "
        "{%0,%1,%2,%3}, {%4,%5,%6,%7}, {%8,%9}, {%0,%1,%2,%3};"
        : "+f"(c[0]), "+f"(c[1]), "+f"(c[2]), "+f"(c[3])
        : "r"(a[0]), "r"(a[1]), "r"(a[2]), "r"(a[3]), "r"(b[0]), "r"(b[1]));
}

// ---------------------------------------------------------------------------
// fp32 -> bf16 hi/lo split (vectorized x4)
// ---------------------------------------------------------------------------
__global__ __launch_bounds__(256) void split_bf16(
    const float* __restrict__ in, __nv_bfloat16* __restrict__ hi,
    __nv_bfloat16* __restrict__ lo, int n4)
{
    int i = blockIdx.x * blockDim.x + threadIdx.x;
    const int stride = gridDim.x * blockDim.x;
    for (; i < n4; i += stride) {
        float4 v = *(const float4*)(in + (size_t)i * 4);
        __nv_bfloat16 h0 = __float2bfloat16(v.x), h1 = __float2bfloat16(v.y);
        __nv_bfloat16 h2 = __float2bfloat16(v.z), h3 = __float2bfloat16(v.w);
        __nv_bfloat162 H0; H0.x = h0; H0.y = h1;
        __nv_bfloat162 H1; H1.x = h2; H1.y = h3;
        __nv_bfloat162 L0, L1;
        L0.x = __float2bfloat16(v.x - __bfloat162float(h0));
        L0.y = __float2bfloat16(v.y - __bfloat162float(h1));
        L1.x = __float2bfloat16(v.z - __bfloat162float(h2));
        L1.y = __float2bfloat16(v.w - __bfloat162float(h3));
        *(__nv_bfloat162*)(hi + (size_t)i * 4)     = H0;
        *(__nv_bfloat162*)(hi + (size_t)i * 4 + 2) = H1;
        *(__nv_bfloat162*)(lo + (size_t)i * 4)     = L0;
        *(__nv_bfloat162*)(lo + (size_t)i * 4 + 2) = L1;
    }
}

// ---------------------------------------------------------------------------
// mma.sync bf16 GEMM: Y[4096,1024] = A @ B^T with split-bf16 3-term K loop.
// CTA 128x128, 8 warps (warp tile 32x64), K-tile 64, cp.async double buffer.
// Smem tile: 128 rows x 128B (64 bf16), chunk-XOR swizzle, ldmatrix.x4 reads.
// ---------------------------------------------------------------------------
#define GEMM_NT 48          // 3 segments * (1024/64)
#define TILEB   16384       // 128 * 128B

__device__ __forceinline__ void stage_g(
    uint32_t s, const __nv_bfloat16* __restrict__ G, int r0, int koff, int tid)
{
#pragma unroll
    for (int i = 0; i < 4; ++i) {
        int idx = tid + i * 256;
        int r = idx >> 3, c = idx & 7;
        uint32_t sw = r * 128 + ((c ^ (r & 7)) << 4);
        const __nv_bfloat16* g = G + (size_t)(r0 + r) * CDIM + koff + c * 8;
        asm volatile("cp.async.cg.shared.global [%0], [%1], 16;"
                     :: "r"(s + sw), "l"(g));
    }
}

__global__ __launch_bounds__(256) void gemm_mma(
    const __nv_bfloat16* __restrict__ Ahi, const __nv_bfloat16* __restrict__ Alo,
    const __nv_bfloat16* __restrict__ Bhi, const __nv_bfloat16* __restrict__ Blo,
    float* __restrict__ Y,
    const float* __restrict__ cv, const float* __restrict__ cb,
    const float* __restrict__ bias)
{
    extern __shared__ char gsm[];
    uint32_t s0 = smem_u32(gsm);
    uint32_t sA[2] = { s0,             s0 + 2 * TILEB };
    uint32_t sB[2] = { s0 + TILEB,     s0 + 3 * TILEB };

    const int tid = threadIdx.x, lane = tid & 31, wid = tid >> 5;
    const int wm = (wid >> 1) * 32;       // warp row offset (0..96)
    const int wn = (wid & 1) * 64;        // warp col offset (0/64)
    const int m0 = blockIdx.y * 128, n0 = blockIdx.x * 128;

    const __nv_bfloat16* segA[3] = { Ahi, Ahi, Alo };
    const __nv_bfloat16* segB[3] = { Bhi, Blo, Bhi };

    float acc[2][8][4];
#pragma unroll
    for (int a = 0; a < 2; ++a)
#pragma unroll
        for (int b = 0; b < 8; ++b)
#pragma unroll
            for (int c = 0; c < 4; ++c) acc[a][b][c] = 0.0f;

    // ldmatrix lane geometry
    const int a_r  = wm + (lane & 7) + ((lane >> 3) & 1) * 8;  // + mt*16
    const int a_kc = lane >> 4;                                // k-chunk half
    const int b_r  = wn + (lane & 7) + (lane >> 4) * 8;        // + p*16
    const int b_kc = (lane >> 3) & 1;

    stage_g(sA[0], segA[0], m0, 0, tid);
    stage_g(sB[0], segB[0], n0, 0, tid);
    asm volatile("cp.async.commit_group;" ::: "memory");

    for (int t = 0; t < GEMM_NT; ++t) {
        const int cur = t & 1, nxt = cur ^ 1;
        if (t + 1 < GEMM_NT) {
            const int tn = t + 1, sg = tn >> 4, ko = (tn & 15) * 64;
            stage_g(sA[nxt], segA[sg], m0, ko, tid);
            stage_g(sB[nxt], segB[sg], n0, ko, tid);
            asm volatile("cp.async.commit_group;" ::: "memory");
            asm volatile("cp.async.wait_group 1;" ::: "memory");
        } else {
            asm volatile("cp.async.wait_group 0;" ::: "memory");
        }
        __syncthreads();

#pragma unroll
        for (int ks = 0; ks < 4; ++ks) {
            uint32_t af[2][4];
#pragma unroll
            for (int mt = 0; mt < 2; ++mt) {
                const int r = a_r + mt * 16;
                uint32_t addr = sA[cur] + r * 128 + (((ks * 2 + a_kc) ^ (r & 7)) << 4);
                ldsm4(af[mt][0], af[mt][1], af[mt][2], af[mt][3], addr);
            }
            uint32_t bf[8][2];
#pragma unroll
            for (int p = 0; p < 4; ++p) {
                const int r = b_r + p * 16;
                uint32_t addr = sB[cur] + r * 128 + (((ks * 2 + b_kc) ^ (r & 7)) << 4);
                ldsm4(bf[2 * p][0], bf[2 * p][1], bf[2 * p + 1][0], bf[2 * p + 1][1], addr);
            }
#pragma unroll
            for (int mt = 0; mt < 2; ++mt)
#pragma unroll
                for (int nt = 0; nt < 8; ++nt)
                    mma16816(acc[mt][nt], af[mt], bf[nt]);
        }
        __syncthreads();
    }

    // Epilogue
    const int er = lane >> 2;
    const int ec = (lane & 3) * 2;
#pragma unroll
    for (int mt = 0; mt < 2; ++mt) {
#pragma unroll
        for (int half = 0; half < 2; ++half) {
            const int row = m0 + wm + mt * 16 + er + half * 8;
            float* yrow = Y + (size_t)row * CDIM;
            const float* cvrow = cv ? cv + (size_t)row * CDIM : (const float*)0;
#pragma unroll
            for (int nt = 0; nt < 8; ++nt) {
                const int col = n0 + wn + nt * 8 + ec;
                float v0 = acc[mt][nt][half * 2 + 0];
                float v1 = acc[mt][nt][half * 2 + 1];
                if (cvrow) {
                    v0 += cb[col]     * cvrow[col];
                    v1 += cb[col + 1] * cvrow[col + 1];
                }
                if (bias) { v0 += bias[col]; v1 += bias[col + 1]; }
                float2 f; f.x = v0; f.y = v1;
                *(float2*)(yrow + col) = f;
            }
        }
    }
}

// ---------------------------------------------------------------------------
// Causal flash attention (fp32). 64x64 tiles, 256 threads, 4x4 thread tiles.
// Q/K/P staged transposed with XOR group swizzle (conflict-free stores AND
// float4 reads). Softmax in log2 domain via ex2.approx.
// ---------------------------------------------------------------------------
#define TSW(d, g) ((((g) ^ ((d) >> 2)) & 15) * 4)

__global__ __launch_bounds__(256) void attn_kernel(
    const float* __restrict__ gq, const float* __restrict__ gk,
    const float* __restrict__ gv, float* __restrict__ go)
{
    extern __shared__ float sm[];
    float* Qt = sm;                 // [64 d][68], transposed + swizzled
    float* Kt = sm + 64 * 68;       // [64 d][68]
    float* Vs = sm + 2 * 64 * 68;   // [64 c][68], natural
    float* Pt = sm + 3 * 64 * 68;   // [64 c][68], transposed + swizzled

    const int tid = threadIdx.x;
    const int tx = tid & 15;
    const int ty = tid >> 4;
    const int qt = blockIdx.x;
    const int bh = blockIdx.y;
    const int b  = bh >> 4;
    const int h  = bh & 15;
    const size_t base = ((size_t)b * T_SEQ) * CDIM + (size_t)h * HD;
    const float SCL = 0.125f * 1.4426950408889634f;   // 1/sqrt(64) * log2(e)

    // Stage Q transposed
#pragma unroll
    for (int it = 0; it < 4; ++it) {
        int idx = tid + it * 256;
        int r = idx >> 4, c4 = (idx & 15) * 4;
        float4 v = *(const float4*)(gq + base + (size_t)(qt * 64 + r) * CDIM + c4);
        Qt[(c4 + 0) * 68 + TSW(c4 + 0, r >> 2) + (r & 3)] = v.x;
        Qt[(c4 + 1) * 68 + TSW(c4 + 1, r >> 2) + (r & 3)] = v.y;
        Qt[(c4 + 2) * 68 + TSW(c4 + 2, r >> 2) + (r & 3)] = v.z;
        Qt[(c4 + 3) * 68 + TSW(c4 + 3, r >> 2) + (r & 3)] = v.w;
    }

    float m_i[4], l_i[4], o[4][4];
#pragma unroll
    for (int i = 0; i < 4; ++i) {
        m_i[i] = -1e30f; l_i[i] = 0.0f;
#pragma unroll
        for (int j = 0; j < 4; ++j) o[i][j] = 0.0f;
    }

    for (int kt = 0; kt <= qt; ++kt) {
        // Stage K transposed + V natural
#pragma unroll
        for (int it = 0; it < 4; ++it) {
            int idx = tid + it * 256;
            int r = idx >> 4, c4 = (idx & 15) * 4;
            size_t g = base + (size_t)(kt * 64 + r) * CDIM + c4;
            float4 kv = *(const float4*)(gk + g);
            Kt[(c4 + 0) * 68 + TSW(c4 + 0, r >> 2) + (r & 3)] = kv.x;
            Kt[(c4 + 1) * 68 + TSW(c4 + 1, r >> 2) + (r & 3)] = kv.y;
            Kt[(c4 + 2) * 68 + TSW(c4 + 2, r >> 2) + (r & 3)] = kv.z;
            Kt[(c4 + 3) * 68 + TSW(c4 + 3, r >> 2) + (r & 3)] = kv.w;
            *(float4*)&Vs[r * 68 + c4] = *(const float4*)(gv + g);
        }
        __syncthreads();

        float s[4][4];
#pragma unroll
        for (int i = 0; i < 4; ++i)
#pragma unroll
            for (int j = 0; j < 4; ++j) s[i][j] = 0.0f;

#pragma unroll 8
        for (int d = 0; d < 64; ++d) {
            float4 a  = *(const float4*)&Qt[d * 68 + TSW(d, ty)];
            float4 bb = *(const float4*)&Kt[d * 68 + TSW(d, tx)];
            s[0][0] = fmaf(a.x, bb.x, s[0][0]); s[0][1] = fmaf(a.x, bb.y, s[0][1]);
            s[0][2] = fmaf(a.x, bb.z, s[0][2]); s[0][3] = fmaf(a.x, bb.w, s[0][3]);
            s[1][0] = fmaf(a.y, bb.x, s[1][0]); s[1][1] = fmaf(a.y, bb.y, s[1][1]);
            s[1][2] = fmaf(a.y, bb.z, s[1][2]); s[1][3] = fmaf(a.y, bb.w, s[1][3]);
            s[2][0] = fmaf(a.z, bb.x, s[2][0]); s[2][1] = fmaf(a.z, bb.y, s[2][1]);
            s[2][2] = fmaf(a.z, bb.z, s[2][2]); s[2][3] = fmaf(a.z, bb.w, s[2][3]);
            s[3][0] = fmaf(a.w, bb.x, s[3][0]); s[3][1] = fmaf(a.w, bb.y, s[3][1]);
            s[3][2] = fmaf(a.w, bb.z, s[3][2]); s[3][3] = fmaf(a.w, bb.w, s[3][3]);
        }

#pragma unroll
        for (int i = 0; i < 4; ++i)
#pragma unroll
            for (int j = 0; j < 4; ++j) s[i][j] *= SCL;

        if (kt == qt) {   // causal mask only on the diagonal tile
#pragma unroll
            for (int i = 0; i < 4; ++i)
#pragma unroll
                for (int j = 0; j < 4; ++j)
                    if (tx * 4 + j > ty * 4 + i) s[i][j] = -1e30f;
        }

        // online softmax (log2 domain), reduce across the 16-lane tx group
#pragma unroll
        for (int i = 0; i < 4; ++i) {
            float rm = fmaxf(fmaxf(s[i][0], s[i][1]), fmaxf(s[i][2], s[i][3]));
#pragma unroll
            for (int off = 8; off; off >>= 1)
                rm = fmaxf(rm, __shfl_xor_sync(0xffffffffu, rm, off));
            float mn = fmaxf(m_i[i], rm);
            float corr = ex2f(m_i[i] - mn);
            float rs = 0.0f;
#pragma unroll
            for (int j = 0; j < 4; ++j) {
                float p = ex2f(s[i][j] - mn);
                s[i][j] = p;
                rs += p;
            }
#pragma unroll
            for (int off = 8; off; off >>= 1)
                rs += __shfl_xor_sync(0xffffffffu, rs, off);
            l_i[i] = l_i[i] * corr + rs;
            m_i[i] = mn;
#pragma unroll
            for (int j = 0; j < 4; ++j) o[i][j] *= corr;
        }
        // store P transposed [c][row] with swizzle
#pragma unroll
        for (int j = 0; j < 4; ++j) {
            const int d = tx * 4 + j;
            const int gbase = d * 68 + TSW(d, ty);
#pragma unroll
            for (int i = 0; i < 4; ++i)
                Pt[gbase + i] = s[i][j];
        }
        __syncthreads();

        // O += P @ V
#pragma unroll 8
        for (int c = 0; c < 64; ++c) {
            float4 p  = *(const float4*)&Pt[c * 68 + TSW(c, ty)];
            float4 vv = *(const float4*)&Vs[c * 68 + tx * 4];
            o[0][0] = fmaf(p.x, vv.x, o[0][0]); o[0][1] = fmaf(p.x, vv.y, o[0][1]);
            o[0][2] = fmaf(p.x, vv.z, o[0][2]); o[0][3] = fmaf(p.x, vv.w, o[0][3]);
            o[1][0] = fmaf(p.y, vv.x, o[1][0]); o[1][1] = fmaf(p.y, vv.y, o[1][1]);
            o[1][2] = fmaf(p.y, vv.z, o[1][2]); o[1][3] = fmaf(p.y, vv.w, o[1][3]);
            o[2][0] = fmaf(p.z, vv.x, o[2][0]); o[2][1] = fmaf(p.z, vv.y, o[2][1]);
            o[2][2] = fmaf(p.z, vv.z, o[2][2]); o[2][3] = fmaf(p.z, vv.w, o[2][3]);
            o[3][0] = fmaf(p.w, vv.x, o[3][0]); o[3][1] = fmaf(p.w, vv.y, o[3][1]);
            o[3][2] = fmaf(p.w, vv.z, o[3][2]); o[3][3] = fmaf(p.w, vv.w, o[3][3]);
        }
        __syncthreads();
    }

#pragma unroll
    for (int i = 0; i < 4; ++i) {
        const float inv = 1.0f / l_i[i];
        const int row = qt * 64 + ty * 4 + i;
        float4 f;
        f.x = o[i][0] * inv; f.y = o[i][1] * inv;
        f.z = o[i][2] * inv; f.w = o[i][3] * inv;
        *(float4*)(go + base + (size_t)row * CDIM + tx * 4) = f;
    }
}

// ---------------------------------------------------------------------------
// Launch.  Inputs: 0:x 1:mask 2:context_vector 3:w_q 4:w_k 5:w_v 6:w_o 7:b_o
//                  8:context_bias    out: f32 [2,2048,1024]
// ---------------------------------------------------------------------------
extern "C" void kernel_launch(void* const* d_in, const int* in_sizes, int n_in,
                              void* d_out, int out_size)
{
    (void)in_sizes; (void)n_in; (void)out_size;
    const float* x  = (const float*)d_in[0];
    const float* cv = (const float*)d_in[2];
    const float* wq = (const float*)d_in[3];
    const float* wk = (const float*)d_in[4];
    const float* wv = (const float*)d_in[5];
    const float* wo = (const float*)d_in[6];
    const float* bo = (const float*)d_in[7];
    const float* cb = (const float*)d_in[8];
    float* out = (float*)d_out;

    float *q, *k, *v, *att;
    __nv_bfloat16 *ahi, *alo, *whi, *wlo;
    cudaGetSymbolAddress((void**)&q,   g_q);
    cudaGetSymbolAddress((void**)&k,   g_k);
    cudaGetSymbolAddress((void**)&v,   g_v);
    cudaGetSymbolAddress((void**)&att, g_att);
    cudaGetSymbolAddress((void**)&ahi, g_ahi);
    cudaGetSymbolAddress((void**)&alo, g_alo);
    cudaGetSymbolAddress((void**)&whi, g_whi);
    cudaGetSymbolAddress((void**)&wlo, g_wlo);

    const int gemm_smem = 4 * TILEB;                     // 65536
    cudaFuncSetAttribute(gemm_mma, cudaFuncAttributeMaxDynamicSharedMemorySize, gemm_smem);
    const int attn_smem = 4 * 64 * 68 * sizeof(float);   // 69632
    cudaFuncSetAttribute(attn_kernel, cudaFuncAttributeMaxDynamicSharedMemorySize, attn_smem);

    const dim3 ggrid(CDIM / 128, MTOK / 128);   // (8, 32)
    const int NX4 = MTOK * CDIM / 4;
    const int NW4 = CDIM * CDIM / 4;

    split_bf16<<<1024, 256>>>(x, ahi, alo, NX4);

    split_bf16<<<512, 256>>>(wq, whi, wlo, NW4);
    gemm_mma<<<ggrid, 256, gemm_smem>>>(ahi, alo, whi, wlo, q, cv, cb, (const float*)0);
    split_bf16<<<512, 256>>>(wk, whi, wlo, NW4);
    gemm_mma<<<ggrid, 256, gemm_smem>>>(ahi, alo, whi, wlo, k, (const float*)0, (const float*)0, (const float*)0);
    split_bf16<<<512, 256>>>(wv, whi, wlo, NW4);
    gemm_mma<<<ggrid, 256, gemm_smem>>>(ahi, alo, whi, wlo, v, (const float*)0, (const float*)0, (const float*)0);

    attn_kernel<<<dim3(T_SEQ / 64, NB * NH), 256, attn_smem>>>(q, k, v, att);

    split_bf16<<<1024, 256>>>(att, ahi, alo, NX4);
    split_bf16<<<512, 256>>>(wo, whi, wlo, NW4);
    gemm_mma<<<ggrid, 256, gemm_smem>>>(ahi, alo, whi, wlo, out, (const float*)0, (const float*)0, bo);
}

// round 4
// speedup vs baseline: 3.6658x; 2.0420x over previous
#include <cuda_runtime.h>
#include <cuda_bf16.h>
#include <math.h>
#include <stdint.h>

#define T_SEQ 2048
#define CDIM  1024
#define NB    2
#define NH    16
#define HD    64
#define MTOK  (NB * T_SEQ)   // 4096 token rows

// ---------------------------------------------------------------------------
// Scratch (static device globals: allocation-free per harness rules)
// ---------------------------------------------------------------------------
__device__ __nv_bfloat16 g_xhi[(size_t)MTOK * CDIM];
__device__ __nv_bfloat16 g_xlo[(size_t)MTOK * CDIM];
__device__ __nv_bfloat16 g_wqh[(size_t)CDIM * CDIM];
__device__ __nv_bfloat16 g_wql[(size_t)CDIM * CDIM];
__device__ __nv_bfloat16 g_wkh[(size_t)CDIM * CDIM];
__device__ __nv_bfloat16 g_wkl[(size_t)CDIM * CDIM];
__device__ __nv_bfloat16 g_wvh[(size_t)CDIM * CDIM];
__device__ __nv_bfloat16 g_wvl[(size_t)CDIM * CDIM];
__device__ __nv_bfloat16 g_woh[(size_t)CDIM * CDIM];
__device__ __nv_bfloat16 g_wol[(size_t)CDIM * CDIM];
__device__ __nv_bfloat16 g_qhi[(size_t)MTOK * CDIM];
__device__ __nv_bfloat16 g_qlo[(size_t)MTOK * CDIM];
__device__ __nv_bfloat16 g_khi[(size_t)MTOK * CDIM];
__device__ __nv_bfloat16 g_klo[(size_t)MTOK * CDIM];
__device__ __nv_bfloat16 g_vhi[(size_t)MTOK * CDIM];
__device__ __nv_bfloat16 g_vlo[(size_t)MTOK * CDIM];
__device__ __nv_bfloat16 g_ahi[(size_t)MTOK * CDIM];
__device__ __nv_bfloat16 g_alo[(size_t)MTOK * CDIM];

// ---------------------------------------------------------------------------
// Helpers
// ---------------------------------------------------------------------------
__device__ __forceinline__ uint32_t smem_u32(const void* p) {
    uint32_t a;
    asm("{ .reg .u64 t; cvta.to.shared.u64 t, %1; cvt.u32.u64 %0, t; }"
        : "=r"(a) : "l"(p));
    return a;
}
__device__ __forceinline__ float ex2f(float x) {
    float y; asm("ex2.approx.ftz.f32 %0, %1;" : "=f"(y) : "f"(x)); return y;
}
__device__ __forceinline__ void ldsm4(uint32_t& r0, uint32_t& r1,
                                      uint32_t& r2, uint32_t& r3, uint32_t addr) {
    asm volatile("ldmatrix.sync.aligned.m8n8.x4.shared.b16 {%0,%1,%2,%3}, [%4];"
                 : "=r"(r0), "=r"(r1), "=r"(r2), "=r"(r3) : "r"(addr));
}
__device__ __forceinline__ void ldsm4t(uint32_t& r0, uint32_t& r1,
                                       uint32_t& r2, uint32_t& r3, uint32_t addr) {
    asm volatile("ldmatrix.sync.aligned.m8n8.x4.trans.shared.b16 {%0,%1,%2,%3}, [%4];"
                 : "=r"(r0), "=r"(r1), "=r"(r2), "=r"(r3) : "r"(addr));
}
__device__ __forceinline__ void mma_bf16(float* c, const uint32_t* a,
                                         uint32_t b0, uint32_t b1) {
    asm volatile(
        "mma.sync.aligned.m16n8k16.row.col.f32.bf16.bf16.f32 "
        "{%0,%1,%2,%3}, {%4,%5,%6,%7}, {%8,%9}, {%0,%1,%2,%3};"
        : "+f"(c[0]), "+f"(c[1]), "+f"(c[2]), "+f"(c[3])
        : "r"(a[0]), "r"(a[1]), "r"(a[2]), "r"(a[3]), "r"(b0), "r"(b1));
}
// pack two floats into bf16x2 (lo in lower 16 bits)
__device__ __forceinline__ uint32_t packbf(float lo, float hi) {
    uint32_t d;
    asm("cvt.rn.bf16x2.f32 %0, %1, %2;" : "=r"(d) : "f"(hi), "f"(lo));
    return d;
}
// split f0,f1 into hi/lo bf16x2 pairs
__device__ __forceinline__ void split2(float f0, float f1, uint32_t& hp, uint32_t& lp) {
    hp = packbf(f0, f1);
    float h0 = __uint_as_float(hp << 16);
    float h1 = __uint_as_float(hp & 0xffff0000u);
    lp = packbf(f0 - h0, f1 - h1);
}

// ---------------------------------------------------------------------------
// fp32 -> bf16 hi/lo split (vectorized x4)
// ---------------------------------------------------------------------------
__global__ __launch_bounds__(256) void split_bf16(
    const float* __restrict__ in, __nv_bfloat16* __restrict__ hi,
    __nv_bfloat16* __restrict__ lo, int n4)
{
    int i = blockIdx.x * blockDim.x + threadIdx.x;
    const int stride = gridDim.x * blockDim.x;
    for (; i < n4; i += stride) {
        float4 v = *(const float4*)(in + (size_t)i * 4);
        uint32_t h01, l01, h23, l23;
        split2(v.x, v.y, h01, l01);
        split2(v.z, v.w, h23, l23);
        uint2 hh; hh.x = h01; hh.y = h23;
        uint2 ll; ll.x = l01; ll.y = l23;
        *(uint2*)(hi + (size_t)i * 4) = hh;
        *(uint2*)(lo + (size_t)i * 4) = ll;
    }
}

// ---------------------------------------------------------------------------
// Shared GEMM machinery: CTA 128x128, 8 warps (32x64 warp tile), K-tile 64,
// cp.async double buffer, chunk-XOR swizzle, split-bf16 3-term K loop.
// ---------------------------------------------------------------------------
#define GEMM_NT 48          // 3 segments * (1024/64)
#define TILEB   16384       // 128 * 128B

__device__ __forceinline__ void stage_g(
    uint32_t s, const __nv_bfloat16* __restrict__ G, int r0, int koff, int tid)
{
#pragma unroll
    for (int i = 0; i < 4; ++i) {
        int idx = tid + i * 256;
        int r = idx >> 3, c = idx & 7;
        uint32_t sw = r * 128 + ((c ^ (r & 7)) << 4);
        const __nv_bfloat16* g = G + (size_t)(r0 + r) * CDIM + koff + c * 8;
        asm volatile("cp.async.cg.shared.global [%0], [%1], 16;"
                     :: "r"(s + sw), "l"(g));
    }
}

// Core mainloop: accumulates 128x128 into acc. A/B given as hi/lo pairs.
__device__ __forceinline__ void gemm_core(
    uint32_t* sA, uint32_t* sB,
    const __nv_bfloat16* Ahi, const __nv_bfloat16* Alo,
    const __nv_bfloat16* Bhi, const __nv_bfloat16* Blo,
    int m0, int n0, int tid, int lane, int wm, int wn,
    float acc[2][8][4])
{
    const __nv_bfloat16* segA[3] = { Ahi, Ahi, Alo };
    const __nv_bfloat16* segB[3] = { Bhi, Blo, Bhi };

    const int a_r  = wm + (lane & 7) + ((lane >> 3) & 1) * 8;
    const int a_kc = lane >> 4;
    const int b_r  = wn + (lane & 7) + (lane >> 4) * 8;
    const int b_kc = (lane >> 3) & 1;

    stage_g(sA[0], segA[0], m0, 0, tid);
    stage_g(sB[0], segB[0], n0, 0, tid);
    asm volatile("cp.async.commit_group;" ::: "memory");

    for (int t = 0; t < GEMM_NT; ++t) {
        const int cur = t & 1, nxt = cur ^ 1;
        if (t + 1 < GEMM_NT) {
            const int tn = t + 1, sg = tn >> 4, ko = (tn & 15) * 64;
            stage_g(sA[nxt], segA[sg], m0, ko, tid);
            stage_g(sB[nxt], segB[sg], n0, ko, tid);
            asm volatile("cp.async.commit_group;" ::: "memory");
            asm volatile("cp.async.wait_group 1;" ::: "memory");
        } else {
            asm volatile("cp.async.wait_group 0;" ::: "memory");
        }
        __syncthreads();

#pragma unroll
        for (int ks = 0; ks < 4; ++ks) {
            uint32_t af[2][4];
#pragma unroll
            for (int mt = 0; mt < 2; ++mt) {
                const int r = a_r + mt * 16;
                uint32_t addr = sA[cur] + r * 128 + (((ks * 2 + a_kc) ^ (r & 7)) << 4);
                ldsm4(af[mt][0], af[mt][1], af[mt][2], af[mt][3], addr);
            }
            uint32_t bf[8][2];
#pragma unroll
            for (int p = 0; p < 4; ++p) {
                const int r = b_r + p * 16;
                uint32_t addr = sB[cur] + r * 128 + (((ks * 2 + b_kc) ^ (r & 7)) << 4);
                ldsm4(bf[2 * p][0], bf[2 * p][1], bf[2 * p + 1][0], bf[2 * p + 1][1], addr);
            }
#pragma unroll
            for (int mt = 0; mt < 2; ++mt)
#pragma unroll
                for (int nt = 0; nt < 8; ++nt)
                    mma_bf16(acc[mt][nt], af[mt], bf[nt][0], bf[nt][1]);
        }
        __syncthreads();
    }
}

// Fused QKV projection: grid.x = 24 (8 n-blocks x {q,k,v}); writes bf16 hi/lo.
__global__ __launch_bounds__(256) void gemm_qkv(
    const __nv_bfloat16* __restrict__ xhi, const __nv_bfloat16* __restrict__ xlo,
    const __nv_bfloat16* __restrict__ wqh, const __nv_bfloat16* __restrict__ wql,
    const __nv_bfloat16* __restrict__ wkh, const __nv_bfloat16* __restrict__ wkl,
    const __nv_bfloat16* __restrict__ wvh, const __nv_bfloat16* __restrict__ wvl,
    __nv_bfloat16* __restrict__ qh, __nv_bfloat16* __restrict__ ql,
    __nv_bfloat16* __restrict__ kh, __nv_bfloat16* __restrict__ kl,
    __nv_bfloat16* __restrict__ vh, __nv_bfloat16* __restrict__ vl,
    const float* __restrict__ cv, const float* __restrict__ cb)
{
    extern __shared__ char gsm[];
    uint32_t s0 = smem_u32(gsm);
    uint32_t sA[2] = { s0,         s0 + 2 * TILEB };
    uint32_t sB[2] = { s0 + TILEB, s0 + 3 * TILEB };

    const int tid = threadIdx.x, lane = tid & 31, wid = tid >> 5;
    const int wm = (wid >> 1) * 32, wn = (wid & 1) * 64;
    const int wsel = blockIdx.x >> 3;
    const int n0 = (blockIdx.x & 7) * 128;
    const int m0 = blockIdx.y * 128;

    const __nv_bfloat16* Bh = (wsel == 0) ? wqh : (wsel == 1) ? wkh : wvh;
    const __nv_bfloat16* Bl = (wsel == 0) ? wql : (wsel == 1) ? wkl : wvl;
    __nv_bfloat16* Oh = (wsel == 0) ? qh : (wsel == 1) ? kh : vh;
    __nv_bfloat16* Ol = (wsel == 0) ? ql : (wsel == 1) ? kl : vl;
    const bool do_cv = (wsel == 0);

    float acc[2][8][4];
#pragma unroll
    for (int a = 0; a < 2; ++a)
#pragma unroll
        for (int b = 0; b < 8; ++b)
#pragma unroll
            for (int c = 0; c < 4; ++c) acc[a][b][c] = 0.0f;

    gemm_core(sA, sB, xhi, xlo, Bh, Bl, m0, n0, tid, lane, wm, wn, acc);

    const int er = lane >> 2, ec = (lane & 3) * 2;
#pragma unroll
    for (int mt = 0; mt < 2; ++mt)
#pragma unroll
        for (int half = 0; half < 2; ++half) {
            const int row = m0 + wm + mt * 16 + er + half * 8;
#pragma unroll
            for (int nt = 0; nt < 8; ++nt) {
                const int col = n0 + wn + nt * 8 + ec;
                float v0 = acc[mt][nt][half * 2 + 0];
                float v1 = acc[mt][nt][half * 2 + 1];
                if (do_cv) {
                    const float* cvr = cv + (size_t)row * CDIM;
                    v0 += cb[col]     * cvr[col];
                    v1 += cb[col + 1] * cvr[col + 1];
                }
                uint32_t hp, lp;
                split2(v0, v1, hp, lp);
                *(uint32_t*)(Oh + (size_t)row * CDIM + col) = hp;
                *(uint32_t*)(Ol + (size_t)row * CDIM + col) = lp;
            }
        }
}

// Output projection: fp32 out + bias
__global__ __launch_bounds__(256) void gemm_out(
    const __nv_bfloat16* __restrict__ Ahi, const __nv_bfloat16* __restrict__ Alo,
    const __nv_bfloat16* __restrict__ Bhi, const __nv_bfloat16* __restrict__ Blo,
    float* __restrict__ Y, const float* __restrict__ bias)
{
    extern __shared__ char gsm[];
    uint32_t s0 = smem_u32(gsm);
    uint32_t sA[2] = { s0,         s0 + 2 * TILEB };
    uint32_t sB[2] = { s0 + TILEB, s0 + 3 * TILEB };

    const int tid = threadIdx.x, lane = tid & 31, wid = tid >> 5;
    const int wm = (wid >> 1) * 32, wn = (wid & 1) * 64;
    const int m0 = blockIdx.y * 128, n0 = blockIdx.x * 128;

    float acc[2][8][4];
#pragma unroll
    for (int a = 0; a < 2; ++a)
#pragma unroll
        for (int b = 0; b < 8; ++b)
#pragma unroll
            for (int c = 0; c < 4; ++c) acc[a][b][c] = 0.0f;

    gemm_core(sA, sB, Ahi, Alo, Bhi, Blo, m0, n0, tid, lane, wm, wn, acc);

    const int er = lane >> 2, ec = (lane & 3) * 2;
#pragma unroll
    for (int mt = 0; mt < 2; ++mt)
#pragma unroll
        for (int half = 0; half < 2; ++half) {
            const int row = m0 + wm + mt * 16 + er + half * 8;
            float* yrow = Y + (size_t)row * CDIM;
#pragma unroll
            for (int nt = 0; nt < 8; ++nt) {
                const int col = n0 + wn + nt * 8 + ec;
                float2 f;
                f.x = acc[mt][nt][half * 2 + 0] + bias[col];
                f.y = acc[mt][nt][half * 2 + 1] + bias[col + 1];
                *(float2*)(yrow + col) = f;
            }
        }
}

// ---------------------------------------------------------------------------
// Causal flash attention via mma.sync bf16 with hi/lo split everywhere.
// CTA: 128 q-rows of one (b,h); 8 warps, each 16 q-rows x 128 k-cols.
// ---------------------------------------------------------------------------
__global__ __launch_bounds__(256) void attn_mma(
    const __nv_bfloat16* __restrict__ qhi, const __nv_bfloat16* __restrict__ qlo,
    const __nv_bfloat16* __restrict__ khi, const __nv_bfloat16* __restrict__ klo,
    const __nv_bfloat16* __restrict__ vhi, const __nv_bfloat16* __restrict__ vlo,
    __nv_bfloat16* __restrict__ ohi, __nv_bfloat16* __restrict__ olo)
{
    extern __shared__ char asmem[];
    const uint32_t s0 = smem_u32(asmem);
    const uint32_t sQh = s0,          sQl = s0 + 16384;
    const uint32_t sKh = s0 + 32768,  sKl = s0 + 49152;
    const uint32_t sVh = s0 + 65536,  sVl = s0 + 81920;

    const int tid = threadIdx.x, lane = tid & 31, wid = tid >> 5;
    const int qt = blockIdx.x;           // 0..15 (128-row q tiles)
    const int bh = blockIdx.y;           // 0..31
    const int b  = bh >> 4, h = bh & 15;
    const float SCL = 0.125f * 1.4426950408889634f;

    const size_t tokbase = (size_t)b * T_SEQ;
    const size_t headoff = (size_t)h * HD;

    // ---- stage Q (hi+lo), 128 rows x 128B each
    {
        const __nv_bfloat16* gh = qhi + (tokbase + qt * 128) * CDIM + headoff;
        const __nv_bfloat16* gl = qlo + (tokbase + qt * 128) * CDIM + headoff;
#pragma unroll
        for (int i = 0; i < 4; ++i) {
            int idx = tid + i * 256;
            int r = idx >> 3, c = idx & 7;
            uint32_t sw = r * 128 + ((c ^ (r & 7)) << 4);
            asm volatile("cp.async.cg.shared.global [%0], [%1], 16;"
                         :: "r"(sQh + sw), "l"(gh + (size_t)r * CDIM + c * 8));
            asm volatile("cp.async.cg.shared.global [%0], [%1], 16;"
                         :: "r"(sQl + sw), "l"(gl + (size_t)r * CDIM + c * 8));
        }
    }
    // ---- stage K/V tile kt=0
    {
        const size_t rb = (tokbase + 0) * CDIM + headoff;
#pragma unroll
        for (int i = 0; i < 4; ++i) {
            int idx = tid + i * 256;
            int r = idx >> 3, c = idx & 7;
            uint32_t sw = r * 128 + ((c ^ (r & 7)) << 4);
            size_t g = rb + (size_t)r * CDIM + c * 8;
            asm volatile("cp.async.cg.shared.global [%0], [%1], 16;" :: "r"(sKh + sw), "l"(khi + g));
            asm volatile("cp.async.cg.shared.global [%0], [%1], 16;" :: "r"(sKl + sw), "l"(klo + g));
            asm volatile("cp.async.cg.shared.global [%0], [%1], 16;" :: "r"(sVh + sw), "l"(vhi + g));
            asm volatile("cp.async.cg.shared.global [%0], [%1], 16;" :: "r"(sVl + sw), "l"(vlo + g));
        }
    }
    asm volatile("cp.async.commit_group;" ::: "memory");
    asm volatile("cp.async.wait_group 0;" ::: "memory");
    __syncthreads();

    // ---- preload Q fragments (fixed for whole CTA)
    uint32_t qhf[4][4], qlf[4][4];
    {
        const int a_r  = wid * 16 + (lane & 7) + ((lane >> 3) & 1) * 8;
        const int a_kc = lane >> 4;
#pragma unroll
        for (int ks = 0; ks < 4; ++ks) {
            const int ch = ks * 2 + a_kc;
            uint32_t sw = a_r * 128 + ((ch ^ (a_r & 7)) << 4);
            ldsm4(qhf[ks][0], qhf[ks][1], qhf[ks][2], qhf[ks][3], sQh + sw);
            ldsm4(qlf[ks][0], qlf[ks][1], qlf[ks][2], qlf[ks][3], sQl + sw);
        }
    }

    float o[8][4];
#pragma unroll
    for (int i = 0; i < 8; ++i)
#pragma unroll
        for (int j = 0; j < 4; ++j) o[i][j] = 0.0f;
    float m_[2] = { -1e30f, -1e30f };
    float l_[2] = { 0.0f, 0.0f };

    const int b_rb = (lane & 7) + ((lane >> 4) << 3);   // + g*16
    const int b_kc = (lane >> 3) & 1;
    const int v_rb = (lane & 7) + (((lane >> 3) & 1) << 3);
    const int v_cs = lane >> 4;

    for (int kt = 0; kt <= qt; ++kt) {
        if (kt > 0) {
            const size_t rb = (tokbase + kt * 128) * CDIM + headoff;
#pragma unroll
            for (int i = 0; i < 4; ++i) {
                int idx = tid + i * 256;
                int r = idx >> 3, c = idx & 7;
                uint32_t sw = r * 128 + ((c ^ (r & 7)) << 4);
                size_t g = rb + (size_t)r * CDIM + c * 8;
                asm volatile("cp.async.cg.shared.global [%0], [%1], 16;" :: "r"(sKh + sw), "l"(khi + g));
                asm volatile("cp.async.cg.shared.global [%0], [%1], 16;" :: "r"(sKl + sw), "l"(klo + g));
                asm volatile("cp.async.cg.shared.global [%0], [%1], 16;" :: "r"(sVh + sw), "l"(vhi + g));
                asm volatile("cp.async.cg.shared.global [%0], [%1], 16;" :: "r"(sVl + sw), "l"(vlo + g));
            }
            asm volatile("cp.async.commit_group;" ::: "memory");
            asm volatile("cp.async.wait_group 0;" ::: "memory");
            __syncthreads();
        }

        // ---- S = Q K^T (3-term split), 16 n8 tiles per warp
        float sc[16][4];
#pragma unroll
        for (int t = 0; t < 16; ++t)
#pragma unroll
            for (int j = 0; j < 4; ++j) sc[t][j] = 0.0f;

#pragma unroll
        for (int ks = 0; ks < 4; ++ks) {
#pragma unroll
            for (int g = 0; g < 8; ++g) {
                const int r = g * 16 + b_rb;
                const int ch = ks * 2 + b_kc;
                uint32_t sw = r * 128 + ((ch ^ (r & 7)) << 4);
                uint32_t kh0, kh1, kh2, kh3, kl0, kl1, kl2, kl3;
                ldsm4(kh0, kh1, kh2, kh3, sKh + sw);
                ldsm4(kl0, kl1, kl2, kl3, sKl + sw);
                mma_bf16(sc[2 * g],     qhf[ks], kh0, kh1);
                mma_bf16(sc[2 * g],     qhf[ks], kl0, kl1);
                mma_bf16(sc[2 * g],     qlf[ks], kh0, kh1);
                mma_bf16(sc[2 * g + 1], qhf[ks], kh2, kh3);
                mma_bf16(sc[2 * g + 1], qhf[ks], kl2, kl3);
                mma_bf16(sc[2 * g + 1], qlf[ks], kh2, kh3);
            }
        }

        // ---- scale + causal mask (diagonal tile only)
        const bool diag = (kt == qt);
#pragma unroll
        for (int t = 0; t < 16; ++t)
#pragma unroll
            for (int j = 0; j < 4; ++j) {
                float v = sc[t][j] * SCL;
                if (diag) {
                    const int col = t * 8 + ((lane & 3) << 1) + (j & 1);
                    const int row = (wid << 4) + (lane >> 2) + ((j >> 1) << 3);
                    if (col > row) v = -1e30f;
                }
                sc[t][j] = v;
            }

        // ---- online softmax (log2 domain); rows reduced over 4-lane groups
#pragma unroll
        for (int hf = 0; hf < 2; ++hf) {
            float mx = -1e30f;
#pragma unroll
            for (int t = 0; t < 16; ++t)
                mx = fmaxf(mx, fmaxf(sc[t][2 * hf], sc[t][2 * hf + 1]));
            mx = fmaxf(mx, __shfl_xor_sync(0xffffffffu, mx, 1));
            mx = fmaxf(mx, __shfl_xor_sync(0xffffffffu, mx, 2));
            const float mn = fmaxf(m_[hf], mx);
            const float corr = ex2f(m_[hf] - mn);
            float rs = 0.0f;
#pragma unroll
            for (int t = 0; t < 16; ++t) {
                float p0 = ex2f(sc[t][2 * hf]     - mn);
                float p1 = ex2f(sc[t][2 * hf + 1] - mn);
                sc[t][2 * hf] = p0; sc[t][2 * hf + 1] = p1;
                rs += p0 + p1;
            }
            rs += __shfl_xor_sync(0xffffffffu, rs, 1);
            rs += __shfl_xor_sync(0xffffffffu, rs, 2);
            l_[hf] = l_[hf] * corr + rs;
            m_[hf] = mn;
#pragma unroll
            for (int nt = 0; nt < 8; ++nt) {
                o[nt][2 * hf]     *= corr;
                o[nt][2 * hf + 1] *= corr;
            }
        }

        // ---- O += P V (3-term split); P fragments built in registers
#pragma unroll
        for (int ks2 = 0; ks2 < 8; ++ks2) {
            uint32_t ph[4], pl[4];
            split2(sc[2 * ks2][0],     sc[2 * ks2][1],     ph[0], pl[0]);
            split2(sc[2 * ks2][2],     sc[2 * ks2][3],     ph[1], pl[1]);
            split2(sc[2 * ks2 + 1][0], sc[2 * ks2 + 1][1], ph[2], pl[2]);
            split2(sc[2 * ks2 + 1][2], sc[2 * ks2 + 1][3], ph[3], pl[3]);
#pragma unroll
            for (int ng = 0; ng < 4; ++ng) {
                const int r = ks2 * 16 + v_rb;
                const int ch = ng * 2 + v_cs;
                uint32_t sw = r * 128 + ((ch ^ (r & 7)) << 4);
                uint32_t vh0, vh1, vh2, vh3, vl0, vl1, vl2, vl3;
                ldsm4t(vh0, vh1, vh2, vh3, sVh + sw);
                ldsm4t(vl0, vl1, vl2, vl3, sVl + sw);
                mma_bf16(o[2 * ng],     ph, vh0, vh1);
                mma_bf16(o[2 * ng],     ph, vl0, vl1);
                mma_bf16(o[2 * ng],     pl, vh0, vh1);
                mma_bf16(o[2 * ng + 1], ph, vh2, vh3);
                mma_bf16(o[2 * ng + 1], ph, vl2, vl3);
                mma_bf16(o[2 * ng + 1], pl, vh2, vh3);
            }
        }
        __syncthreads();   // K/V smem consumed; safe to restage
    }

    // ---- epilogue: normalize, split hi/lo, store
#pragma unroll
    for (int hf = 0; hf < 2; ++hf) {
        const float inv = 1.0f / l_[hf];
        const int row = qt * 128 + wid * 16 + (lane >> 2) + hf * 8;
        __nv_bfloat16* oh = ohi + (tokbase + row) * CDIM + headoff;
        __nv_bfloat16* ol = olo + (tokbase + row) * CDIM + headoff;
#pragma unroll
        for (int nt = 0; nt < 8; ++nt) {
            const int col = nt * 8 + (lane & 3) * 2;
            float f0 = o[nt][2 * hf]     * inv;
            float f1 = o[nt][2 * hf + 1] * inv;
            uint32_t hp, lp;
            split2(f0, f1, hp, lp);
            *(uint32_t*)(oh + col) = hp;
            *(uint32_t*)(ol + col) = lp;
        }
    }
}

// ---------------------------------------------------------------------------
// Launch.  Inputs: 0:x 1:mask 2:context_vector 3:w_q 4:w_k 5:w_v 6:w_o 7:b_o
//                  8:context_bias    out: f32 [2,2048,1024]
// ---------------------------------------------------------------------------
extern "C" void kernel_launch(void* const* d_in, const int* in_sizes, int n_in,
                              void* d_out, int out_size)
{
    (void)in_sizes; (void)n_in; (void)out_size;
    const float* x  = (const float*)d_in[0];
    const float* cv = (const float*)d_in[2];
    const float* wq = (const float*)d_in[3];
    const float* wk = (const float*)d_in[4];
    const float* wv = (const float*)d_in[5];
    const float* wo = (const float*)d_in[6];
    const float* bo = (const float*)d_in[7];
    const float* cb = (const float*)d_in[8];
    float* out = (float*)d_out;

    __nv_bfloat16 *xhi, *xlo, *wqh, *wql, *wkh, *wkl, *wvh, *wvl, *woh, *wol;
    __nv_bfloat16 *qh, *ql, *kh, *kl, *vh, *vl, *ah, *al;
    cudaGetSymbolAddress((void**)&xhi, g_xhi); cudaGetSymbolAddress((void**)&xlo, g_xlo);
    cudaGetSymbolAddress((void**)&wqh, g_wqh); cudaGetSymbolAddress((void**)&wql, g_wql);
    cudaGetSymbolAddress((void**)&wkh, g_wkh); cudaGetSymbolAddress((void**)&wkl, g_wkl);
    cudaGetSymbolAddress((void**)&wvh, g_wvh); cudaGetSymbolAddress((void**)&wvl, g_wvl);
    cudaGetSymbolAddress((void**)&woh, g_woh); cudaGetSymbolAddress((void**)&wol, g_wol);
    cudaGetSymbolAddress((void**)&qh,  g_qhi); cudaGetSymbolAddress((void**)&ql,  g_qlo);
    cudaGetSymbolAddress((void**)&kh,  g_khi); cudaGetSymbolAddress((void**)&kl,  g_klo);
    cudaGetSymbolAddress((void**)&vh,  g_vhi); cudaGetSymbolAddress((void**)&vl,  g_vlo);
    cudaGetSymbolAddress((void**)&ah,  g_ahi); cudaGetSymbolAddress((void**)&al,  g_alo);

    const int gemm_smem = 4 * TILEB;   // 65536
    cudaFuncSetAttribute(gemm_qkv, cudaFuncAttributeMaxDynamicSharedMemorySize, gemm_smem);
    cudaFuncSetAttribute(gemm_out, cudaFuncAttributeMaxDynamicSharedMemorySize, gemm_smem);
    const int attn_smem = 6 * 16384;   // 98304
    cudaFuncSetAttribute(attn_mma, cudaFuncAttributeMaxDynamicSharedMemorySize, attn_smem);

    const int NX4 = MTOK * CDIM / 4;
    const int NW4 = CDIM * CDIM / 4;

    split_bf16<<<1024, 256>>>(x,  xhi, xlo, NX4);
    split_bf16<<<512, 256>>>(wq, wqh, wql, NW4);
    split_bf16<<<512, 256>>>(wk, wkh, wkl, NW4);
    split_bf16<<<512, 256>>>(wv, wvh, wvl, NW4);
    split_bf16<<<512, 256>>>(wo, woh, wol, NW4);

    gemm_qkv<<<dim3(24, MTOK / 128), 256, gemm_smem>>>(
        xhi, xlo, wqh, wql, wkh, wkl, wvh, wvl,
        qh, ql, kh, kl, vh, vl, cv, cb);

    attn_mma<<<dim3(T_SEQ / 128, NB * NH), 256, attn_smem>>>(
        qh, ql, kh, kl, vh, vl, ah, al);

    gemm_out<<<dim3(CDIM / 128, MTOK / 128), 256, gemm_smem>>>(
        ah, al, woh, wol, out, bo);
}